// round 1
// baseline (speedup 1.0000x reference)
#include <cuda_runtime.h>

// Problem-fixed shapes (setup_inputs): R=4000, C=20, K=3, H=W=1024, h=w=128.
#define HH 1024
#define WW 1024
#define CC 20
#define hh 128
#define ww 128
#define C1 21   // refine_result last dim = C+1
#define EPSF 1e-6f

// Scratch (static __device__ globals: no allocation at runtime).
__device__ float g_D[CC][HH][WW];     // per-channel delta/partial-scan image (~84 MB)
__device__ float g_Rm[CC][hh][ww];    // sampled (stride-8) integral image values
__device__ int   g_minb[CC];          // per-channel min of M (float bits)
__device__ int   g_maxb[CC];          // per-channel max of M (float bits)
__device__ float g_part[CC][4];       // per-channel loss partials: px, py, nx, ny

__device__ __forceinline__ void atomicMinF(int* addr, float v) {
    int old = *addr;
    while (__int_as_float(old) > v) {
        int assumed = old;
        old = atomicCAS(addr, assumed, __float_as_int(v));
        if (old == assumed) break;
    }
}
__device__ __forceinline__ void atomicMaxF(int* addr, float v) {
    int old = *addr;
    while (__int_as_float(old) < v) {
        int assumed = old;
        old = atomicCAS(addr, assumed, __float_as_int(v));
        if (old == assumed) break;
    }
}

// ---------------------------------------------------------------------------
// 1) Zero D for valid channels; init per-channel min/max.
//    grid (1024, CC), 256 thr; each thread zeroes one float4.
__global__ void k_init(const int* __restrict__ labels) {
    int c = blockIdx.y;
    if (blockIdx.x == 0 && threadIdx.x == 0) {
        g_minb[c] = __float_as_int(3.4e38f);
        g_maxb[c] = __float_as_int(-3.4e38f);
    }
    if (labels[c] != 1) return;
    int i = blockIdx.x * blockDim.x + threadIdx.x;   // < 1024*256 = HH*WW/4
    reinterpret_cast<float4*>(&g_D[c][0][0])[i] = make_float4(0.f, 0.f, 0.f, 0.f);
}

// ---------------------------------------------------------------------------
// 2) Scores + 4-corner scatter. One thread per (roi, class).
__global__ void k_scatter(const float* __restrict__ refine,
                          const float* __restrict__ rois,
                          const int*   __restrict__ labels,
                          int R) {
    int idx = blockIdx.x * blockDim.x + threadIdx.x;
    if (idx >= R * CC) return;
    int r = idx / CC, c = idx % CC;      // contiguous in c -> coalesced refine reads
    if (labels[c] != 1) return;          // scores *= vmf
    int base = r * C1 + c + 1;           // avg[:,1:]
    float s = (refine[base] + refine[R * C1 + base] + refine[2 * R * C1 + base]) * (1.0f / 3.0f);
    if (s < 0.3f) return;                // SCORE_THRES: < -> 0 (no scatter)
    int x1 = (int)rois[r * 5 + 1];
    int y1 = (int)rois[r * 5 + 2];
    int x2 = (int)rois[r * 5 + 3];
    int y2 = (int)rois[r * 5 + 4];
    // Reference's D is (H+1,W+1) but row/col H,W are clipped away by M[:H,:W];
    // skipping out-of-range corners is equivalent.
    if (y1 < HH && x1 < WW) atomicAdd(&g_D[c][y1][x1],  s);
    if (y1 < HH && x2 < WW) atomicAdd(&g_D[c][y1][x2], -s);
    if (y2 < HH && x1 < WW) atomicAdd(&g_D[c][y2][x1], -s);
    if (y2 < HH && x2 < WW) atomicAdd(&g_D[c][y2][x2],  s);
}

// ---------------------------------------------------------------------------
// 3) Per-row inclusive prefix sum (cumsum along x). grid (HH, CC), 256 thr.
//    Each thread owns one float4 (4 consecutive elements).
__global__ void k_rowscan(const int* __restrict__ labels) {
    int c = blockIdx.y;
    if (labels[c] != 1) return;
    int y = blockIdx.x, t = threadIdx.x;
    float4* row = reinterpret_cast<float4*>(&g_D[c][y][0]);
    float4 v = row[t];
    v.y += v.x; v.z += v.y; v.w += v.z;
    __shared__ float sh[256];
    sh[t] = v.w;
    __syncthreads();
    // Hillis-Steele inclusive scan over 256 thread-sums.
    for (int off = 1; off < 256; off <<= 1) {
        float tmp = (t >= off) ? sh[t - off] : 0.0f;
        __syncthreads();
        sh[t] += tmp;
        __syncthreads();
    }
    float excl = (t == 0) ? 0.0f : sh[t - 1];
    v.x += excl; v.y += excl; v.z += excl; v.w += excl;
    row[t] = v;
}

// ---------------------------------------------------------------------------
// 4) Column scan (cumsum along y), FUSED with: full-image per-channel min/max
//    and stride-8 sampling into g_Rm. M is never stored.
//    grid (WW/256, CC), 256 thr; thread = one column.
__global__ void k_colscan(const int* __restrict__ labels) {
    int c = blockIdx.y;
    if (labels[c] != 1) return;
    int t = threadIdx.x;
    int x = blockIdx.x * 256 + t;
    float run = 0.f, mn = 3.4e38f, mx = -3.4e38f;
    bool samp_x = ((x & 7) == 0);
    #pragma unroll 4
    for (int y = 0; y < HH; ++y) {
        run += g_D[c][y][x];                 // coalesced: consecutive threads, consecutive x
        mn = fminf(mn, run);
        mx = fmaxf(mx, run);
        if (samp_x && ((y & 7) == 0)) g_Rm[c][y >> 3][x >> 3] = run;
    }
    __shared__ float smn[256], smx[256];
    smn[t] = mn; smx[t] = mx;
    __syncthreads();
    for (int off = 128; off; off >>= 1) {
        if (t < off) {
            smn[t] = fminf(smn[t], smn[t + off]);
            smx[t] = fmaxf(smx[t], smx[t + off]);
        }
        __syncthreads();
    }
    if (t == 0) {
        atomicMinF(&g_minb[c], smn[0]);
        atomicMaxF(&g_maxb[c], smx[0]);
    }
}

// ---------------------------------------------------------------------------
// 5) Per-channel loss partials. grid (CC), 128 thr.
__global__ void k_loss(const float* __restrict__ blob,
                       const int*   __restrict__ labels) {
    int c = blockIdx.x, t = threadIdx.x;   // t in [0,128)
    bool valid = (labels[c] == 1);
    const float* B = blob + c * hh * ww;

    // mx_b[j]: max over rows i at column j=t (coalesced pass).
    float cmax = 0.f;
    for (int i = 0; i < hh; ++i) cmax = fmaxf(cmax, B[i * ww + t]);
    // my_b[i]: max over cols j at row i=t (L2-resident second pass).
    float rmax = 0.f;
    for (int j = 0; j < ww; ++j) rmax = fmaxf(rmax, B[t * ww + j]);
    cmax = fminf(fmaxf(cmax, EPSF), 1.f - EPSF);   // clip (monotone, commutes with max)
    rmax = fminf(fmaxf(rmax, EPSF), 1.f - EPSF);

    float vx, vy;
    if (valid) {
        float mnv = __int_as_float(g_minb[c]);
        float mxv = __int_as_float(g_maxb[c]);
        // normalized >= 0.5  <=>  raw >= mn + 0.5*(mx - mn + eps)
        float thr = mnv + 0.5f * (mxv - mnv + EPSF);
        float scol = -3.4e38f, srow = -3.4e38f;
        for (int i = 0; i < hh; ++i) scol = fmaxf(scol, g_Rm[c][i][t]);
        for (int j = 0; j < ww; ++j) srow = fmaxf(srow, g_Rm[c][t][j]);
        vx = (scol >= thr) ? -logf(cmax) : 0.f;
        vy = (srow >= thr) ? -logf(rmax) : 0.f;
    } else {
        vx = -logf(1.f - cmax);
        vy = -logf(1.f - rmax);
    }

    __shared__ float sx[128], sy[128];
    sx[t] = vx; sy[t] = vy;
    __syncthreads();
    for (int off = 64; off; off >>= 1) {
        if (t < off) { sx[t] += sx[t + off]; sy[t] += sy[t + off]; }
        __syncthreads();
    }
    if (t == 0) {
        if (valid) { g_part[c][0] = sx[0]; g_part[c][1] = sy[0]; g_part[c][2] = 0.f; g_part[c][3] = 0.f; }
        else       { g_part[c][0] = 0.f;   g_part[c][1] = 0.f;   g_part[c][2] = sx[0]; g_part[c][3] = sy[0]; }
    }
}

// ---------------------------------------------------------------------------
// 6) Finalize: combine partials with normalizers, write scalar.
__global__ void k_final(const int* __restrict__ labels, float* __restrict__ out) {
    if (threadIdx.x != 0) return;
    float vc = 0.f;
    for (int c = 0; c < CC; ++c) vc += (labels[c] == 1) ? 1.f : 0.f;
    float nvc = (float)CC - vc;
    float px = 0.f, py = 0.f, nx = 0.f, ny = 0.f;
    for (int c = 0; c < CC; ++c) {
        px += g_part[c][0]; py += g_part[c][1];
        nx += g_part[c][2]; ny += g_part[c][3];
    }
    out[0] = px / (vc * (float)ww) + nx / (nvc * (float)ww)
           + py / (vc * (float)hh) + ny / (nvc * (float)hh);
}

// ---------------------------------------------------------------------------
extern "C" void kernel_launch(void* const* d_in, const int* in_sizes, int n_in,
                              void* d_out, int out_size) {
    // metadata order: mil_result(unused), refine_result, blob_conv, rois, labels, H, W
    const float* refine = (const float*)d_in[1];
    const float* blob   = (const float*)d_in[2];
    const float* rois   = (const float*)d_in[3];
    const int*   labels = (const int*)  d_in[4];
    int R = in_sizes[3] / 5;

    k_init   <<<dim3(HH * WW / (256 * 4), CC), 256>>>(labels);
    int total = R * CC;
    k_scatter<<<(total + 255) / 256, 256>>>(refine, rois, labels, R);
    k_rowscan<<<dim3(HH, CC), 256>>>(labels);
    k_colscan<<<dim3(WW / 256, CC), 256>>>(labels);
    k_loss   <<<CC, 128>>>(blob, labels);
    k_final  <<<1, 32>>>(labels, (float*)d_out);
}

// round 2
// speedup vs baseline: 2.6696x; 2.6696x over previous
#include <cuda_runtime.h>

// Problem-fixed shapes (setup_inputs): R=4000, C=20, K=3, H=W=1024, h=w=128.
#define HH 1024
#define WW 1024
#define CC 20
#define hh 128
#define ww 128
#define C1 21     // refine_result last dim = C+1
#define EPSF 1e-6f
#define NSEG 32   // column-scan segments
#define SEGH (HH / NSEG)   // 32 rows per segment

// Scratch (static __device__ globals: no allocation at runtime).
__device__ float g_D[CC][HH][WW];        // per-channel delta / row-scanned image
__device__ float g_seg[CC][NSEG][WW];    // per-segment column sums
__device__ float g_Rm[CC][hh][ww];       // sampled (stride-8) integral image values
__device__ int   g_minb[CC];             // per-channel min of M (float bits)
__device__ int   g_maxb[CC];             // per-channel max of M (float bits)
__device__ float g_part[CC][4];          // per-channel loss partials: px, py, nx, ny

__device__ __forceinline__ void atomicMinF(int* addr, float v) {
    int old = *addr;
    while (__int_as_float(old) > v) {
        int assumed = old;
        old = atomicCAS(addr, assumed, __float_as_int(v));
        if (old == assumed) break;
    }
}
__device__ __forceinline__ void atomicMaxF(int* addr, float v) {
    int old = *addr;
    while (__int_as_float(old) < v) {
        int assumed = old;
        old = atomicCAS(addr, assumed, __float_as_int(v));
        if (old == assumed) break;
    }
}

// ---------------------------------------------------------------------------
// 1) Zero D for valid channels; init per-channel min/max.
__global__ void k_init(const int* __restrict__ labels) {
    int c = blockIdx.y;
    if (blockIdx.x == 0 && threadIdx.x == 0) {
        g_minb[c] = __float_as_int(3.4e38f);
        g_maxb[c] = __float_as_int(-3.4e38f);
    }
    if (labels[c] != 1) return;
    int i = blockIdx.x * blockDim.x + threadIdx.x;   // HH*WW/4 float4s
    reinterpret_cast<float4*>(&g_D[c][0][0])[i] = make_float4(0.f, 0.f, 0.f, 0.f);
}

// ---------------------------------------------------------------------------
// 2) Scores + 4-corner scatter. One thread per (roi, class).
__global__ void k_scatter(const float* __restrict__ refine,
                          const float* __restrict__ rois,
                          const int*   __restrict__ labels,
                          int R) {
    int idx = blockIdx.x * blockDim.x + threadIdx.x;
    if (idx >= R * CC) return;
    int r = idx / CC, c = idx % CC;
    if (labels[c] != 1) return;          // scores *= vmf
    int base = r * C1 + c + 1;           // avg[:,1:]
    float s = (refine[base] + refine[R * C1 + base] + refine[2 * R * C1 + base]) * (1.0f / 3.0f);
    if (s < 0.3f) return;                // SCORE_THRES
    int x1 = (int)rois[r * 5 + 1];
    int y1 = (int)rois[r * 5 + 2];
    int x2 = (int)rois[r * 5 + 3];
    int y2 = (int)rois[r * 5 + 4];
    // D is (H+1,W+1) in the reference but row/col H,W are clipped by M[:H,:W].
    if (y1 < HH && x1 < WW) atomicAdd(&g_D[c][y1][x1],  s);
    if (y1 < HH && x2 < WW) atomicAdd(&g_D[c][y1][x2], -s);
    if (y2 < HH && x1 < WW) atomicAdd(&g_D[c][y2][x1], -s);
    if (y2 < HH && x2 < WW) atomicAdd(&g_D[c][y2][x2],  s);
}

// ---------------------------------------------------------------------------
// 3) Per-row inclusive prefix sum (cumsum along x). grid (HH, CC), 256 thr.
__global__ void k_rowscan(const int* __restrict__ labels) {
    int c = blockIdx.y;
    if (labels[c] != 1) return;
    int y = blockIdx.x, t = threadIdx.x;
    float4* row = reinterpret_cast<float4*>(&g_D[c][y][0]);
    float4 v = row[t];
    v.y += v.x; v.z += v.y; v.w += v.z;
    __shared__ float sh[256];
    sh[t] = v.w;
    __syncthreads();
    for (int off = 1; off < 256; off <<= 1) {
        float tmp = (t >= off) ? sh[t - off] : 0.0f;
        __syncthreads();
        sh[t] += tmp;
        __syncthreads();
    }
    float excl = (t == 0) ? 0.0f : sh[t - 1];
    v.x += excl; v.y += excl; v.z += excl; v.w += excl;
    row[t] = v;
}

// ---------------------------------------------------------------------------
// 4) Per-segment column sums: g_seg[c][seg][x] = sum of 32 rows at column x.
//    grid (WW/256, NSEG, CC). Independent loads -> high MLP, latency hidden.
__global__ void k_segsum(const int* __restrict__ labels) {
    int c = blockIdx.z;
    if (labels[c] != 1) return;
    int seg = blockIdx.y;
    int x = blockIdx.x * 256 + threadIdx.x;
    float s = 0.f;
    #pragma unroll
    for (int r = 0; r < SEGH; ++r)
        s += g_D[c][seg * SEGH + r][x];
    g_seg[c][seg][x] = s;
}

// ---------------------------------------------------------------------------
// 5) Segmented column scan: base offset = sum of prior segment sums (computed
//    in-block from g_seg), then a 32-long running scan with fused min/max and
//    stride-8 sampling. grid (WW/256, NSEG, CC).
__global__ void k_colscan2(const int* __restrict__ labels) {
    int c = blockIdx.z;
    if (labels[c] != 1) return;
    int seg = blockIdx.y;
    int t = threadIdx.x;
    int x = blockIdx.x * 256 + t;

    float off = 0.f;
    #pragma unroll 8
    for (int s = 0; s < seg; ++s) off += g_seg[c][s][x];

    float run = off, mn = 3.4e38f, mx = -3.4e38f;
    bool samp_x = ((x & 7) == 0);
    #pragma unroll
    for (int r = 0; r < SEGH; ++r) {
        int y = seg * SEGH + r;
        run += g_D[c][y][x];
        mn = fminf(mn, run);
        mx = fmaxf(mx, run);
        if (samp_x && ((y & 7) == 0)) g_Rm[c][y >> 3][x >> 3] = run;
    }

    __shared__ float smn[256], smx[256];
    smn[t] = mn; smx[t] = mx;
    __syncthreads();
    for (int o = 128; o; o >>= 1) {
        if (t < o) {
            smn[t] = fminf(smn[t], smn[t + o]);
            smx[t] = fmaxf(smx[t], smx[t + o]);
        }
        __syncthreads();
    }
    if (t == 0) {
        atomicMinF(&g_minb[c], smn[0]);
        atomicMaxF(&g_maxb[c], smx[0]);
    }
}

// ---------------------------------------------------------------------------
// 6) Per-channel loss partials. grid (CC), 128 thr.
__global__ void k_loss(const float* __restrict__ blob,
                       const int*   __restrict__ labels) {
    int c = blockIdx.x, t = threadIdx.x;
    bool valid = (labels[c] == 1);
    const float* B = blob + c * hh * ww;

    float cmax = 0.f;
    for (int i = 0; i < hh; ++i) cmax = fmaxf(cmax, B[i * ww + t]);
    float rmax = 0.f;
    for (int j = 0; j < ww; ++j) rmax = fmaxf(rmax, B[t * ww + j]);
    cmax = fminf(fmaxf(cmax, EPSF), 1.f - EPSF);
    rmax = fminf(fmaxf(rmax, EPSF), 1.f - EPSF);

    float vx, vy;
    if (valid) {
        float mnv = __int_as_float(g_minb[c]);
        float mxv = __int_as_float(g_maxb[c]);
        float thr = mnv + 0.5f * (mxv - mnv + EPSF);  // normalized >= 0.5
        float scol = -3.4e38f, srow = -3.4e38f;
        for (int i = 0; i < hh; ++i) scol = fmaxf(scol, g_Rm[c][i][t]);
        for (int j = 0; j < ww; ++j) srow = fmaxf(srow, g_Rm[c][t][j]);
        vx = (scol >= thr) ? -logf(cmax) : 0.f;
        vy = (srow >= thr) ? -logf(rmax) : 0.f;
    } else {
        vx = -logf(1.f - cmax);
        vy = -logf(1.f - rmax);
    }

    __shared__ float sx[128], sy[128];
    sx[t] = vx; sy[t] = vy;
    __syncthreads();
    for (int o = 64; o; o >>= 1) {
        if (t < o) { sx[t] += sx[t + o]; sy[t] += sy[t + o]; }
        __syncthreads();
    }
    if (t == 0) {
        if (valid) { g_part[c][0] = sx[0]; g_part[c][1] = sy[0]; g_part[c][2] = 0.f; g_part[c][3] = 0.f; }
        else       { g_part[c][0] = 0.f;   g_part[c][1] = 0.f;   g_part[c][2] = sx[0]; g_part[c][3] = sy[0]; }
    }
}

// ---------------------------------------------------------------------------
// 7) Finalize: combine partials with normalizers, write scalar.
__global__ void k_final(const int* __restrict__ labels, float* __restrict__ out) {
    if (threadIdx.x != 0) return;
    float vc = 0.f;
    for (int c = 0; c < CC; ++c) vc += (labels[c] == 1) ? 1.f : 0.f;
    float nvc = (float)CC - vc;
    float px = 0.f, py = 0.f, nx = 0.f, ny = 0.f;
    for (int c = 0; c < CC; ++c) {
        px += g_part[c][0]; py += g_part[c][1];
        nx += g_part[c][2]; ny += g_part[c][3];
    }
    out[0] = px / (vc * (float)ww) + nx / (nvc * (float)ww)
           + py / (vc * (float)hh) + ny / (nvc * (float)hh);
}

// ---------------------------------------------------------------------------
extern "C" void kernel_launch(void* const* d_in, const int* in_sizes, int n_in,
                              void* d_out, int out_size) {
    // metadata order: mil_result(unused), refine_result, blob_conv, rois, labels, H, W
    const float* refine = (const float*)d_in[1];
    const float* blob   = (const float*)d_in[2];
    const float* rois   = (const float*)d_in[3];
    const int*   labels = (const int*)  d_in[4];
    int R = in_sizes[3] / 5;

    k_init    <<<dim3(HH * WW / (256 * 4), CC), 256>>>(labels);
    int total = R * CC;
    k_scatter <<<(total + 255) / 256, 256>>>(refine, rois, labels, R);
    k_rowscan <<<dim3(HH, CC), 256>>>(labels);
    k_segsum  <<<dim3(WW / 256, NSEG, CC), 256>>>(labels);
    k_colscan2<<<dim3(WW / 256, NSEG, CC), 256>>>(labels);
    k_loss    <<<CC, 128>>>(blob, labels);
    k_final   <<<1, 32>>>(labels, (float*)d_out);
}